// round 14
// baseline (speedup 1.0000x reference)
#include <cuda_runtime.h>
#include <cuda_fp16.h>
#include <math.h>
#include <stdint.h>

#define NN 100000
#define EE 1600000
#define NB 98   // scan blocks: ceil(NN/1024)

typedef unsigned long long ull;

// K dims (halfs): layer1 = 8*32 (A) + 32 (x) + 32 (pad) = 320 ; layer2 = 8*64 + 64 (h) = 576
#define K1 320
#define N1 128          // h (0..63) + skip (64..127)
#define K2 576
#define N2 64

// ---- scratch (device globals) ----
__device__ __half g_Ah[((size_t)NN + 256) * 640];  // fp16 A rows; stride 320 (L1) or 576 (L2)
__device__ __half g_Wt1[N1 * K1];                  // B operand layer1 [o][k]
__device__ __half g_Wt2[N2 * K2];                  // B operand layer2 [o][k]
__device__ float g_h[(size_t)NN * 64];             // h1 act, then h2 pre-BN
__device__ float g_skip[(size_t)NN * 64];          // skip pre-BN
__device__ int   g_deg[NN];
__device__ int   g_off[NN + 1];
__device__ int   g_cur[NN];
__device__ int   g_bsum[128];
__device__ uint4 g_erec[EE];                       // {src, u0, u1, u2} fp32 bits, sorted by dst (25.6 MB)
__device__ float g_sum[192];
__device__ float g_sq[192];

// ---- f32x2 helpers ----
__device__ __forceinline__ ull pk2(float x, float y) {
    ull r; asm("mov.b64 %0, {%1, %2};" : "=l"(r) : "f"(x), "f"(y)); return r;
}
__device__ __forceinline__ void fma2(ull& d, ull a, ull b) {
    asm("fma.rn.f32x2 %0, %1, %2, %3;" : "=l"(d) : "l"(a), "l"(b), "l"(d));
}
__device__ __forceinline__ float2 upk2(ull v) {
    float2 f; asm("mov.b64 {%0, %1}, %2;" : "=f"(f.x), "=f"(f.y) : "l"(v)); return f;
}

// ---------------- CSR build ----------------
__global__ void __launch_bounds__(256) hist_kernel(const int* __restrict__ ei) {
    int e = blockIdx.x * 256 + threadIdx.x;
    if (e >= EE) return;
    atomicAdd(&g_deg[__ldg(&ei[EE + e])], 1);
}

// parallel scan, stage 1: per-block exclusive scan of 1024 degs + block total
__global__ void __launch_bounds__(1024) scan_partial_kernel() {
    __shared__ int wsum[32];
    int tid = threadIdx.x, lane = tid & 31, wid = tid >> 5;
    int i = blockIdx.x * 1024 + tid;
    int v = (i < NN) ? g_deg[i] : 0;
    int inc = v;
#pragma unroll
    for (int d = 1; d < 32; d <<= 1) {
        int t = __shfl_up_sync(0xffffffffu, inc, d);
        if (lane >= d) inc += t;
    }
    if (lane == 31) wsum[wid] = inc;
    __syncthreads();
    if (wid == 0) {
        int w = wsum[lane];
        int winc = w;
#pragma unroll
        for (int d = 1; d < 32; d <<= 1) {
            int t = __shfl_up_sync(0xffffffffu, winc, d);
            if (lane >= d) winc += t;
        }
        wsum[lane] = winc - w;
        if (lane == 31) g_bsum[blockIdx.x] = winc;
    }
    __syncthreads();
    if (i < NN) g_off[i] = wsum[wid] + inc - v;
}

// parallel scan, stage 2: add block base
__global__ void __launch_bounds__(1024) scan_add_kernel() {
    __shared__ int sbase;
    int tid = threadIdx.x;
    if (tid == 0) {
        int b = 0;
        for (int j = 0; j < (int)blockIdx.x; j++) b += g_bsum[j];
        sbase = b;
        if (blockIdx.x == 0) {
            int tot = 0;
            for (int j = 0; j < NB; j++) tot += g_bsum[j];
            g_off[NN] = tot;
        }
    }
    __syncthreads();
    int i = blockIdx.x * 1024 + tid;
    if (i < NN) {
        int o = g_off[i] + sbase;
        g_off[i] = o;
        g_cur[i] = o;
    }
}

__global__ void __launch_bounds__(256) scatter_kernel(const int* __restrict__ ei,
                                                      const float* __restrict__ ea) {
    int e = blockIdx.x * 256 + threadIdx.x;
    if (e >= EE) return;
    int src = __ldg(&ei[e]);
    int dst = __ldg(&ei[EE + e]);
    float u0 = __ldg(&ea[e * 3 + 0]);
    float u1 = __ldg(&ea[e * 3 + 1]);
    float u2 = __ldg(&ea[e * 3 + 2]);
    int pos = atomicAdd(&g_cur[dst], 1);
    g_erec[pos] = make_uint4((unsigned)src, __float_as_uint(u0),
                             __float_as_uint(u1), __float_as_uint(u2));
}

// ---------------- edge agg layer1: 2 warps per node (even/odd edge split) ----------------
__global__ void __launch_bounds__(256) edge_agg1_kernel(const float* __restrict__ x) {
    __shared__ float sbuf[4][32][9];   // odd-warp partials, padded (9) for bank spread
    int w = threadIdx.x >> 5, lane = threadIdx.x & 31;
    int pair = w >> 1, half = w & 1;
    int n = blockIdx.x * 4 + pair;
    int start = 0, end = 0;
    if (n < NN) { start = __ldg(&g_off[n]); end = __ldg(&g_off[n + 1]); }
    ull acc[4];
#pragma unroll
    for (int j = 0; j < 4; j++) acc[j] = 0ull;
    for (int e = start + half; e < end; e += 2) {
        uint4 r = __ldg(&g_erec[e]);
        int src = (int)r.x;
        float u0 = __uint_as_float(r.y);
        float u1 = __uint_as_float(r.z);
        float u2 = __uint_as_float(r.w);
        float xv = __ldg(&x[(size_t)src * 32 + lane]);
        float v0 = 1.f - u0, v1 = 1.f - u1, v2 = 1.f - u2;
        float pa = v1 * v2, pb = u1 * v2, pc = v1 * u2, pd = u1 * u2;
        ull ap = pk2(xv, xv);
        fma2(acc[0], ap, pk2(v0 * pa, u0 * pa));
        fma2(acc[1], ap, pk2(v0 * pb, u0 * pb));
        fma2(acc[2], ap, pk2(v0 * pc, u0 * pc));
        fma2(acc[3], ap, pk2(v0 * pd, u0 * pd));
    }
    if (half) {
#pragma unroll
        for (int j = 0; j < 4; j++) {
            float2 v = upk2(acc[j]);
            sbuf[pair][lane][2 * j]     = v.x;
            sbuf[pair][lane][2 * j + 1] = v.y;
        }
    }
    __syncthreads();
    if (!half && n < NN) {
        int deg = end - start;
        float inv = 1.0f / (float)(deg > 0 ? deg : 1);
        __half* row = g_Ah + (size_t)n * K1;
#pragma unroll
        for (int j = 0; j < 4; j++) {
            float2 v = upk2(acc[j]);
            v.x += sbuf[pair][lane][2 * j];
            v.y += sbuf[pair][lane][2 * j + 1];
            row[(2 * j) * 32 + lane]     = __float2half(v.x * inv);
            row[(2 * j + 1) * 32 + lane] = __float2half(v.y * inv);
        }
        row[256 + lane] = __float2half(__ldg(&x[(size_t)n * 32 + lane]));
        row[288 + lane] = __float2half(0.f);
    }
}

// ---------------- edge agg layer2: 2 warps per node (even/odd edge split) ----------------
__global__ void __launch_bounds__(256) edge_agg2_kernel() {
    __shared__ float sbuf[4][32][17];  // odd-warp partials (16 floats), padded to 17
    int w = threadIdx.x >> 5, lane = threadIdx.x & 31;
    int pair = w >> 1, half = w & 1;
    int n = blockIdx.x * 4 + pair;
    int start = 0, end = 0;
    if (n < NN) { start = __ldg(&g_off[n]); end = __ldg(&g_off[n + 1]); }
    ull acc[8];
#pragma unroll
    for (int k = 0; k < 8; k++) acc[k] = 0ull;
    const float2* hb2 = reinterpret_cast<const float2*>(g_h);
    for (int e = start + half; e < end; e += 2) {
        uint4 r = __ldg(&g_erec[e]);
        int src = (int)r.x;
        float u0 = __uint_as_float(r.y);
        float u1 = __uint_as_float(r.z);
        float u2 = __uint_as_float(r.w);
        float2 f = __ldg(&hb2[(size_t)src * 32 + lane]);   // feats 2*lane, 2*lane+1
        float v0 = 1.f - u0, v1 = 1.f - u1, v2 = 1.f - u2;
        float pa = v1 * v2, pb = u1 * v2, pc = v1 * u2, pd = u1 * u2;
        float b0 = v0 * pa, b1 = u0 * pa, b2 = v0 * pb, b3 = u0 * pb;
        float b4 = v0 * pc, b5 = u0 * pc, b6 = v0 * pd, b7 = u0 * pd;
        ull ap = pk2(f.x, f.y);
        fma2(acc[0], ap, pk2(b0, b0));
        fma2(acc[1], ap, pk2(b1, b1));
        fma2(acc[2], ap, pk2(b2, b2));
        fma2(acc[3], ap, pk2(b3, b3));
        fma2(acc[4], ap, pk2(b4, b4));
        fma2(acc[5], ap, pk2(b5, b5));
        fma2(acc[6], ap, pk2(b6, b6));
        fma2(acc[7], ap, pk2(b7, b7));
    }
    if (half) {
#pragma unroll
        for (int k = 0; k < 8; k++) {
            float2 v = upk2(acc[k]);
            sbuf[pair][lane][2 * k]     = v.x;
            sbuf[pair][lane][2 * k + 1] = v.y;
        }
    }
    __syncthreads();
    if (!half && n < NN) {
        int deg = end - start;
        float inv = 1.0f / (float)(deg > 0 ? deg : 1);
        __half2* row = reinterpret_cast<__half2*>(g_Ah + (size_t)n * K2);
#pragma unroll
        for (int k = 0; k < 8; k++) {
            float2 v = upk2(acc[k]);
            v.x += sbuf[pair][lane][2 * k];
            v.y += sbuf[pair][lane][2 * k + 1];
            row[k * 32 + lane] = __floats2half2_rn(v.x * inv, v.y * inv);
        }
    }
}

// ---------------- wprep: fp16 B operands [o][k] ----------------
__global__ void __launch_bounds__(256) wprep_kernel(const float* __restrict__ W1,
                                                    const float* __restrict__ root1,
                                                    const float* __restrict__ Wsk,
                                                    const float* __restrict__ W2,
                                                    const float* __restrict__ root2) {
    int idx = blockIdx.x * 256 + threadIdx.x;
    if (idx < N1 * K1) {
        int o = idx / K1, k = idx % K1;
        float v = 0.f;
        if (o < 64) {
            if (k < 256)      v = W1[(k >> 5) * 2048 + (k & 31) * 64 + o];
            else if (k < 288) v = root1[(k - 256) * 64 + o];
        } else {
            if (k >= 256 && k < 288) v = Wsk[(k - 256) * 64 + (o - 64)];
        }
        g_Wt1[idx] = __float2half(v);
    } else {
        int i2 = idx - N1 * K1;
        if (i2 >= N2 * K2) return;
        int o = i2 / K2, k = i2 % K2;
        float v = (k < 512) ? W2[(k >> 6) * 4096 + (k & 63) * 64 + o]
                            : root2[(k - 512) * 64 + o];
        g_Wt2[i2] = __float2half(v);
    }
}

// ---------------- HMMA GEMM: out[rows_pb][Ncols] per block = A @ Wt^T, fused BN stats ----------------
__global__ void __launch_bounds__(256) gemm_mma_kernel(const __half* __restrict__ Aglob, int K,
                                                       const __half* __restrict__ Wt, int Ncols,
                                                       int rows_pb,
                                                       float* __restrict__ out0,
                                                       float* __restrict__ out1,
                                                       int sumbase) {
    extern __shared__ __half Bs[];
    __shared__ float s_sum[128], s_sq[128];
    int tid = threadIdx.x, warp = tid >> 5, lane = tid & 31;
    int gid = lane >> 2, t4 = lane & 3;
    int Kpad = K + 8;

    for (int i = tid; i < Ncols * (K / 8); i += 256) {
        int o = i / (K / 8), p = i % (K / 8);
        *reinterpret_cast<uint4*>(&Bs[o * Kpad + p * 8]) =
            *reinterpret_cast<const uint4*>(&Wt[(size_t)o * K + p * 8]);
    }
    if (tid < 128) { s_sum[tid] = 0.f; s_sq[tid] = 0.f; }
    __syncthreads();

    int rwarps = rows_pb >> 5;                 // 4 or 8
    int roww = (warp & (rwarps - 1)) * 32;
    int colw = (warp / rwarps) * 64;
    int nbase = blockIdx.x * rows_pb + roww;

    float c[2][8][4];
#pragma unroll
    for (int rt = 0; rt < 2; rt++)
#pragma unroll
        for (int nt = 0; nt < 8; nt++)
#pragma unroll
            for (int q = 0; q < 4; q++) c[rt][nt][q] = 0.f;

    int ksteps = K >> 4;
    for (int ks = 0; ks < ksteps; ks++) {
        int k0 = ks * 16;
        uint32_t a[2][4];
#pragma unroll
        for (int rt = 0; rt < 2; rt++) {
            const __half* ar = Aglob + (size_t)(nbase + rt * 16 + gid) * K + k0 + t4 * 2;
            a[rt][0] = *reinterpret_cast<const uint32_t*>(ar);
            a[rt][2] = *reinterpret_cast<const uint32_t*>(ar + 8);
            const __half* ar8 = ar + (size_t)8 * K;
            a[rt][1] = *reinterpret_cast<const uint32_t*>(ar8);
            a[rt][3] = *reinterpret_cast<const uint32_t*>(ar8 + 8);
        }
#pragma unroll
        for (int nt = 0; nt < 8; nt++) {
            const __half* bp = Bs + (colw + nt * 8 + gid) * Kpad + k0 + t4 * 2;
            uint32_t b0 = *reinterpret_cast<const uint32_t*>(bp);
            uint32_t b1 = *reinterpret_cast<const uint32_t*>(bp + 8);
#pragma unroll
            for (int rt = 0; rt < 2; rt++) {
                asm volatile(
                    "mma.sync.aligned.m16n8k16.row.col.f32.f16.f16.f32 "
                    "{%0,%1,%2,%3}, {%4,%5,%6,%7}, {%8,%9}, {%0,%1,%2,%3};"
                    : "+f"(c[rt][nt][0]), "+f"(c[rt][nt][1]),
                      "+f"(c[rt][nt][2]), "+f"(c[rt][nt][3])
                    : "r"(a[rt][0]), "r"(a[rt][1]), "r"(a[rt][2]), "r"(a[rt][3]),
                      "r"(b0), "r"(b1));
            }
        }
    }

    float ls[16], lq[16];
#pragma unroll
    for (int j = 0; j < 16; j++) { ls[j] = 0.f; lq[j] = 0.f; }
#pragma unroll
    for (int rt = 0; rt < 2; rt++) {
        int r0 = nbase + rt * 16 + gid;
        int r1 = r0 + 8;
#pragma unroll
        for (int nt = 0; nt < 8; nt++) {
            int col = colw + nt * 8 + t4 * 2;
            float v0 = c[rt][nt][0], v1 = c[rt][nt][1];
            float v2 = c[rt][nt][2], v3 = c[rt][nt][3];
            if (r0 < NN) {
                float* dst = (col < 64) ? (out0 + (size_t)r0 * 64 + col)
                                        : (out1 + (size_t)r0 * 64 + col - 64);
                *reinterpret_cast<float2*>(dst) = make_float2(v0, v1);
                ls[nt * 2] += v0; lq[nt * 2] += v0 * v0;
                ls[nt * 2 + 1] += v1; lq[nt * 2 + 1] += v1 * v1;
            }
            if (r1 < NN) {
                float* dst = (col < 64) ? (out0 + (size_t)r1 * 64 + col)
                                        : (out1 + (size_t)r1 * 64 + col - 64);
                *reinterpret_cast<float2*>(dst) = make_float2(v2, v3);
                ls[nt * 2] += v2; lq[nt * 2] += v2 * v2;
                ls[nt * 2 + 1] += v3; lq[nt * 2 + 1] += v3 * v3;
            }
        }
    }
#pragma unroll
    for (int nt = 0; nt < 8; nt++) {
#pragma unroll
        for (int j = 0; j < 2; j++) {
            int col = colw + nt * 8 + t4 * 2 + j;
            atomicAdd(&s_sum[col], ls[nt * 2 + j]);
            atomicAdd(&s_sq[col], lq[nt * 2 + j]);
        }
    }
    __syncthreads();
    if (tid < Ncols) {
        atomicAdd(&g_sum[sumbase + tid], s_sum[tid]);
        atomicAdd(&g_sq[sumbase + tid], s_sq[tid]);
    }
}

// ---------------- bn+elu on h1 (grid-stride, scale/shift computed in-block from slot 0) ----------------
__global__ void __launch_bounds__(256) bnelu_kernel(const float* __restrict__ g1,
                                                    const float* __restrict__ b1) {
    __shared__ float sc[64], sh[64];
    int tid = threadIdx.x;
    if (tid < 64) {
        float mu  = g_sum[tid] * (1.0f / NN);
        float var = g_sq[tid] * (1.0f / NN) - mu * mu;
        float s = g1[tid] * rsqrtf(var + 1e-5f);
        sc[tid] = s;
        sh[tid] = b1[tid] - mu * s;
    }
    __syncthreads();
    for (int i = blockIdx.x * 256 + tid; i < NN * 64; i += gridDim.x * 256) {
        int o = i & 63;
        int n = i >> 6;
        float v = g_h[i] * sc[o] + sh[o];
        float e = (v > 0.f) ? v : expm1f(v);
        g_h[i] = e;
        g_Ah[(size_t)n * K2 + 512 + o] = __float2half(e);
    }
}

// ---------------- final: out = elu( BN(h2) + BN(skip) ), scale/shift from slots 1,2 ----------------
__global__ void __launch_bounds__(256) final_kernel(const float* __restrict__ gsk,
                                                    const float* __restrict__ bsk,
                                                    const float* __restrict__ g2,
                                                    const float* __restrict__ b2,
                                                    float* __restrict__ out) {
    __shared__ float sc1[64], sh1[64], sc2[64], sh2[64];
    int tid = threadIdx.x;
    if (tid < 64) {
        float mu  = g_sum[64 + tid] * (1.0f / NN);
        float var = g_sq[64 + tid] * (1.0f / NN) - mu * mu;
        float s = gsk[tid] * rsqrtf(var + 1e-5f);
        sc1[tid] = s;
        sh1[tid] = bsk[tid] - mu * s;
        mu  = g_sum[128 + tid] * (1.0f / NN);
        var = g_sq[128 + tid] * (1.0f / NN) - mu * mu;
        s = g2[tid] * rsqrtf(var + 1e-5f);
        sc2[tid] = s;
        sh2[tid] = b2[tid] - mu * s;
    }
    __syncthreads();
    for (int i = blockIdx.x * 256 + tid; i < NN * 64; i += gridDim.x * 256) {
        int o = i & 63;
        float h2 = g_h[i] * sc2[o] + sh2[o];
        float s  = g_skip[i] * sc1[o] + sh1[o];
        float v = h2 + s;
        out[i] = (v > 0.f) ? v : expm1f(v);
    }
}

extern "C" void kernel_launch(void* const* d_in, const int* in_sizes, int n_in,
                              void* d_out, int out_size) {
    const float* x     = (const float*)d_in[0];
    const int*   ei    = (const int*)d_in[1];
    const float* ea    = (const float*)d_in[2];
    const float* W1    = (const float*)d_in[3];
    const float* root1 = (const float*)d_in[4];
    const float* g1    = (const float*)d_in[5];
    const float* b1    = (const float*)d_in[6];
    const float* W2    = (const float*)d_in[7];
    const float* root2 = (const float*)d_in[8];
    const float* g2    = (const float*)d_in[9];
    const float* b2    = (const float*)d_in[10];
    const float* Wsk   = (const float*)d_in[11];
    const float* gsk   = (const float*)d_in[12];
    const float* bsk   = (const float*)d_in[13];
    float* out = (float*)d_out;

    void *deg_p, *sum_p, *sq_p, *ah_p, *wt1_p, *wt2_p, *h_p, *skip_p;
    cudaGetSymbolAddress(&deg_p, g_deg);
    cudaGetSymbolAddress(&sum_p, g_sum);
    cudaGetSymbolAddress(&sq_p, g_sq);
    cudaGetSymbolAddress(&ah_p, g_Ah);
    cudaGetSymbolAddress(&wt1_p, g_Wt1);
    cudaGetSymbolAddress(&wt2_p, g_Wt2);
    cudaGetSymbolAddress(&h_p, g_h);
    cudaGetSymbolAddress(&skip_p, g_skip);

    int smem1 = N1 * (K1 + 8) * 2;   // 83,968 B
    int smem2 = N2 * (K2 + 8) * 2;   // 74,752 B
    cudaFuncSetAttribute(gemm_mma_kernel, cudaFuncAttributeMaxDynamicSharedMemorySize, smem1);

    cudaMemsetAsync(deg_p, 0, sizeof(int) * NN, 0);
    cudaMemsetAsync(sum_p, 0, sizeof(float) * 192, 0);
    cudaMemsetAsync(sq_p, 0, sizeof(float) * 192, 0);

    // CSR build (parallel scan)
    hist_kernel<<<(EE + 255) / 256, 256>>>(ei);
    scan_partial_kernel<<<NB, 1024>>>();
    scan_add_kernel<<<NB, 1024>>>();
    scatter_kernel<<<(EE + 255) / 256, 256>>>(ei, ea);

    // ---- layer 1 ----  (agg1 is the 5th kernel; window may land on scatter or agg1)
    edge_agg1_kernel<<<(NN + 3) / 4, 256>>>(x);
    wprep_kernel<<<(N1 * K1 + N2 * K2 + 255) / 256, 256>>>(W1, root1, Wsk, W2, root2);
    gemm_mma_kernel<<<(NN + 127) / 128, 256, smem1>>>((const __half*)ah_p, K1,
                                                      (const __half*)wt1_p, N1, 128,
                                                      (float*)h_p, (float*)skip_p, 0);
    bnelu_kernel<<<1184, 256>>>(g1, b1);

    // ---- layer 2 ----
    edge_agg2_kernel<<<(NN + 3) / 4, 256>>>();
    gemm_mma_kernel<<<(NN + 255) / 256, 256, smem2>>>((const __half*)ah_p, K2,
                                                      (const __half*)wt2_p, N2, 256,
                                                      (float*)h_p, (float*)h_p, 128);
    final_kernel<<<1184, 256>>>(gsk, bsk, g2, b2, out);
    (void)n_in; (void)in_sizes; (void)out_size;
}

// round 15
// speedup vs baseline: 1.1153x; 1.1153x over previous
#include <cuda_runtime.h>
#include <cuda_fp16.h>
#include <math.h>
#include <stdint.h>

#define NN 100000
#define EE 1600000
#define NB 98   // scan blocks: ceil(NN/1024)

typedef unsigned long long ull;

// K dims (halfs): layer1 = 8*32 (A) + 32 (x) + 32 (pad) = 320 ; layer2 = 8*64 + 64 (h) = 576
#define K1 320
#define N1 128          // h (0..63) + skip (64..127)
#define K2 576
#define N2 64

// ---- scratch (device globals) ----
__device__ __half g_Ah[((size_t)NN + 256) * 640];  // fp16 A rows; stride 320 (L1) or 576 (L2)
__device__ __half g_Wt1[N1 * K1];                  // B operand layer1 [o][k]
__device__ __half g_Wt2[N2 * K2];                  // B operand layer2 [o][k]
__device__ float g_h[(size_t)NN * 64];             // h1 act, then h2 pre-BN
__device__ float g_skip[(size_t)NN * 64];          // skip pre-BN
__device__ int   g_deg[NN];
__device__ int   g_off[NN + 1];
__device__ int   g_cur[NN];
__device__ int   g_bsum[128];
__device__ uint4 g_erec[EE];                       // {src, u0, u1, u2} fp32 bits, sorted by dst (25.6 MB)
__device__ float g_sum[192];
__device__ float g_sq[192];

// ---- f32x2 helpers ----
__device__ __forceinline__ ull pk2(float x, float y) {
    ull r; asm("mov.b64 %0, {%1, %2};" : "=l"(r) : "f"(x), "f"(y)); return r;
}
__device__ __forceinline__ void fma2(ull& d, ull a, ull b) {
    asm("fma.rn.f32x2 %0, %1, %2, %3;" : "=l"(d) : "l"(a), "l"(b), "l"(d));
}
__device__ __forceinline__ float2 upk2(ull v) {
    float2 f; asm("mov.b64 {%0, %1}, %2;" : "=f"(f.x), "=f"(f.y) : "l"(v)); return f;
}

// ---------------- CSR build ----------------
__global__ void __launch_bounds__(256) hist_kernel(const int* __restrict__ ei) {
    int e = blockIdx.x * 256 + threadIdx.x;
    if (e >= EE) return;
    atomicAdd(&g_deg[__ldg(&ei[EE + e])], 1);
}

// parallel scan, stage 1: per-block exclusive scan of 1024 degs + block total
__global__ void __launch_bounds__(1024) scan_partial_kernel() {
    __shared__ int wsum[32];
    int tid = threadIdx.x, lane = tid & 31, wid = tid >> 5;
    int i = blockIdx.x * 1024 + tid;
    int v = (i < NN) ? g_deg[i] : 0;
    int inc = v;
#pragma unroll
    for (int d = 1; d < 32; d <<= 1) {
        int t = __shfl_up_sync(0xffffffffu, inc, d);
        if (lane >= d) inc += t;
    }
    if (lane == 31) wsum[wid] = inc;
    __syncthreads();
    if (wid == 0) {
        int w = wsum[lane];
        int winc = w;
#pragma unroll
        for (int d = 1; d < 32; d <<= 1) {
            int t = __shfl_up_sync(0xffffffffu, winc, d);
            if (lane >= d) winc += t;
        }
        wsum[lane] = winc - w;
        if (lane == 31) g_bsum[blockIdx.x] = winc;
    }
    __syncthreads();
    if (i < NN) g_off[i] = wsum[wid] + inc - v;
}

// parallel scan, stage 2: add block base
__global__ void __launch_bounds__(1024) scan_add_kernel() {
    __shared__ int sbase;
    int tid = threadIdx.x;
    if (tid == 0) {
        int b = 0;
        for (int j = 0; j < (int)blockIdx.x; j++) b += g_bsum[j];
        sbase = b;
        if (blockIdx.x == 0) {
            int tot = 0;
            for (int j = 0; j < NB; j++) tot += g_bsum[j];
            g_off[NN] = tot;
        }
    }
    __syncthreads();
    int i = blockIdx.x * 1024 + tid;
    if (i < NN) {
        int o = g_off[i] + sbase;
        g_off[i] = o;
        g_cur[i] = o;
    }
}

__global__ void __launch_bounds__(256) scatter_kernel(const int* __restrict__ ei,
                                                      const float* __restrict__ ea) {
    int e = blockIdx.x * 256 + threadIdx.x;
    if (e >= EE) return;
    int src = __ldg(&ei[e]);
    int dst = __ldg(&ei[EE + e]);
    float u0 = __ldg(&ea[e * 3 + 0]);
    float u1 = __ldg(&ea[e * 3 + 1]);
    float u2 = __ldg(&ea[e * 3 + 2]);
    int pos = atomicAdd(&g_cur[dst], 1);
    g_erec[pos] = make_uint4((unsigned)src, __float_as_uint(u0),
                             __float_as_uint(u1), __float_as_uint(u2));
}

// ---- basis from record ----
__device__ __forceinline__ void basis8(uint4 r, float* b) {
    float u0 = __uint_as_float(r.y);
    float u1 = __uint_as_float(r.z);
    float u2 = __uint_as_float(r.w);
    float v0 = 1.f - u0, v1 = 1.f - u1, v2 = 1.f - u2;
    float pa = v1 * v2, pb = u1 * v2, pc = v1 * u2, pd = u1 * u2;
    b[0] = v0 * pa; b[1] = u0 * pa; b[2] = v0 * pb; b[3] = u0 * pb;
    b[4] = v0 * pc; b[5] = u0 * pc; b[6] = v0 * pd; b[7] = u0 * pd;
}

// ---------------- edge agg layer1 -> fp16 A rows (stride K1), unroll-2 front-batched ----------------
__global__ void __launch_bounds__(256) edge_agg1_kernel(const float* __restrict__ x) {
    int wid = threadIdx.x >> 5, lane = threadIdx.x & 31;
    int n = blockIdx.x * 8 + wid;
    if (n >= NN) return;
    int start = __ldg(&g_off[n]), end = __ldg(&g_off[n + 1]);
    ull acc[4];
#pragma unroll
    for (int j = 0; j < 4; j++) acc[j] = 0ull;
    int e = start;
    for (; e + 1 < end; e += 2) {
        uint4 ra = __ldg(&g_erec[e]);
        uint4 rb = __ldg(&g_erec[e + 1]);
        float xa = __ldg(&x[(size_t)(int)ra.x * 32 + lane]);
        float xb = __ldg(&x[(size_t)(int)rb.x * 32 + lane]);
        float ba[8], bb[8];
        basis8(ra, ba);
        basis8(rb, bb);
        ull apA = pk2(xa, xa);
        fma2(acc[0], apA, pk2(ba[0], ba[1]));
        fma2(acc[1], apA, pk2(ba[2], ba[3]));
        fma2(acc[2], apA, pk2(ba[4], ba[5]));
        fma2(acc[3], apA, pk2(ba[6], ba[7]));
        ull apB = pk2(xb, xb);
        fma2(acc[0], apB, pk2(bb[0], bb[1]));
        fma2(acc[1], apB, pk2(bb[2], bb[3]));
        fma2(acc[2], apB, pk2(bb[4], bb[5]));
        fma2(acc[3], apB, pk2(bb[6], bb[7]));
    }
    if (e < end) {
        uint4 r = __ldg(&g_erec[e]);
        float xv = __ldg(&x[(size_t)(int)r.x * 32 + lane]);
        float b[8];
        basis8(r, b);
        ull ap = pk2(xv, xv);
        fma2(acc[0], ap, pk2(b[0], b[1]));
        fma2(acc[1], ap, pk2(b[2], b[3]));
        fma2(acc[2], ap, pk2(b[4], b[5]));
        fma2(acc[3], ap, pk2(b[6], b[7]));
    }
    int deg = end - start;
    float inv = 1.0f / (float)(deg > 0 ? deg : 1);
    __half* row = g_Ah + (size_t)n * K1;
#pragma unroll
    for (int j = 0; j < 4; j++) {
        float2 v = upk2(acc[j]);
        row[(2 * j) * 32 + lane]     = __float2half(v.x * inv);
        row[(2 * j + 1) * 32 + lane] = __float2half(v.y * inv);
    }
    row[256 + lane] = __float2half(__ldg(&x[(size_t)n * 32 + lane]));
    row[288 + lane] = __float2half(0.f);
}

// ---------------- edge agg layer2 (fp32 h gather) -> fp16 A rows (stride K2), unroll-2 ----------------
__global__ void __launch_bounds__(256) edge_agg2_kernel() {
    int wid = threadIdx.x >> 5, lane = threadIdx.x & 31;
    int n = blockIdx.x * 8 + wid;
    if (n >= NN) return;
    int start = __ldg(&g_off[n]), end = __ldg(&g_off[n + 1]);
    ull acc[8];
#pragma unroll
    for (int k = 0; k < 8; k++) acc[k] = 0ull;
    const float2* hb2 = reinterpret_cast<const float2*>(g_h);
    int e = start;
    for (; e + 1 < end; e += 2) {
        uint4 ra = __ldg(&g_erec[e]);
        uint4 rb = __ldg(&g_erec[e + 1]);
        float2 fa = __ldg(&hb2[(size_t)(int)ra.x * 32 + lane]);
        float2 fb = __ldg(&hb2[(size_t)(int)rb.x * 32 + lane]);
        float ba[8], bb[8];
        basis8(ra, ba);
        basis8(rb, bb);
        ull apA = pk2(fa.x, fa.y);
#pragma unroll
        for (int k = 0; k < 8; k++) fma2(acc[k], apA, pk2(ba[k], ba[k]));
        ull apB = pk2(fb.x, fb.y);
#pragma unroll
        for (int k = 0; k < 8; k++) fma2(acc[k], apB, pk2(bb[k], bb[k]));
    }
    if (e < end) {
        uint4 r = __ldg(&g_erec[e]);
        float2 f = __ldg(&hb2[(size_t)(int)r.x * 32 + lane]);
        float b[8];
        basis8(r, b);
        ull ap = pk2(f.x, f.y);
#pragma unroll
        for (int k = 0; k < 8; k++) fma2(acc[k], ap, pk2(b[k], b[k]));
    }
    int deg = end - start;
    float inv = 1.0f / (float)(deg > 0 ? deg : 1);
    __half2* row = reinterpret_cast<__half2*>(g_Ah + (size_t)n * K2);
#pragma unroll
    for (int k = 0; k < 8; k++) {
        float2 v = upk2(acc[k]);
        row[k * 32 + lane] = __floats2half2_rn(v.x * inv, v.y * inv);
    }
}

// ---------------- wprep: fp16 B operands [o][k] ----------------
__global__ void __launch_bounds__(256) wprep_kernel(const float* __restrict__ W1,
                                                    const float* __restrict__ root1,
                                                    const float* __restrict__ Wsk,
                                                    const float* __restrict__ W2,
                                                    const float* __restrict__ root2) {
    int idx = blockIdx.x * 256 + threadIdx.x;
    if (idx < N1 * K1) {
        int o = idx / K1, k = idx % K1;
        float v = 0.f;
        if (o < 64) {
            if (k < 256)      v = W1[(k >> 5) * 2048 + (k & 31) * 64 + o];
            else if (k < 288) v = root1[(k - 256) * 64 + o];
        } else {
            if (k >= 256 && k < 288) v = Wsk[(k - 256) * 64 + (o - 64)];
        }
        g_Wt1[idx] = __float2half(v);
    } else {
        int i2 = idx - N1 * K1;
        if (i2 >= N2 * K2) return;
        int o = i2 / K2, k = i2 % K2;
        float v = (k < 512) ? W2[(k >> 6) * 4096 + (k & 63) * 64 + o]
                            : root2[(k - 512) * 64 + o];
        g_Wt2[i2] = __float2half(v);
    }
}

// ---------------- HMMA GEMM: out[rows_pb][Ncols] per block = A @ Wt^T, fused BN stats ----------------
__global__ void __launch_bounds__(256) gemm_mma_kernel(const __half* __restrict__ Aglob, int K,
                                                       const __half* __restrict__ Wt, int Ncols,
                                                       int rows_pb,
                                                       float* __restrict__ out0,
                                                       float* __restrict__ out1,
                                                       int sumbase) {
    extern __shared__ __half Bs[];
    __shared__ float s_sum[128], s_sq[128];
    int tid = threadIdx.x, warp = tid >> 5, lane = tid & 31;
    int gid = lane >> 2, t4 = lane & 3;
    int Kpad = K + 8;

    for (int i = tid; i < Ncols * (K / 8); i += 256) {
        int o = i / (K / 8), p = i % (K / 8);
        *reinterpret_cast<uint4*>(&Bs[o * Kpad + p * 8]) =
            *reinterpret_cast<const uint4*>(&Wt[(size_t)o * K + p * 8]);
    }
    if (tid < 128) { s_sum[tid] = 0.f; s_sq[tid] = 0.f; }
    __syncthreads();

    int rwarps = rows_pb >> 5;                 // 4 or 8
    int roww = (warp & (rwarps - 1)) * 32;
    int colw = (warp / rwarps) * 64;
    int nbase = blockIdx.x * rows_pb + roww;

    float c[2][8][4];
#pragma unroll
    for (int rt = 0; rt < 2; rt++)
#pragma unroll
        for (int nt = 0; nt < 8; nt++)
#pragma unroll
            for (int q = 0; q < 4; q++) c[rt][nt][q] = 0.f;

    int ksteps = K >> 4;
    for (int ks = 0; ks < ksteps; ks++) {
        int k0 = ks * 16;
        uint32_t a[2][4];
#pragma unroll
        for (int rt = 0; rt < 2; rt++) {
            const __half* ar = Aglob + (size_t)(nbase + rt * 16 + gid) * K + k0 + t4 * 2;
            a[rt][0] = *reinterpret_cast<const uint32_t*>(ar);
            a[rt][2] = *reinterpret_cast<const uint32_t*>(ar + 8);
            const __half* ar8 = ar + (size_t)8 * K;
            a[rt][1] = *reinterpret_cast<const uint32_t*>(ar8);
            a[rt][3] = *reinterpret_cast<const uint32_t*>(ar8 + 8);
        }
#pragma unroll
        for (int nt = 0; nt < 8; nt++) {
            const __half* bp = Bs + (colw + nt * 8 + gid) * Kpad + k0 + t4 * 2;
            uint32_t b0 = *reinterpret_cast<const uint32_t*>(bp);
            uint32_t b1 = *reinterpret_cast<const uint32_t*>(bp + 8);
#pragma unroll
            for (int rt = 0; rt < 2; rt++) {
                asm volatile(
                    "mma.sync.aligned.m16n8k16.row.col.f32.f16.f16.f32 "
                    "{%0,%1,%2,%3}, {%4,%5,%6,%7}, {%8,%9}, {%0,%1,%2,%3};"
                    : "+f"(c[rt][nt][0]), "+f"(c[rt][nt][1]),
                      "+f"(c[rt][nt][2]), "+f"(c[rt][nt][3])
                    : "r"(a[rt][0]), "r"(a[rt][1]), "r"(a[rt][2]), "r"(a[rt][3]),
                      "r"(b0), "r"(b1));
            }
        }
    }

    float ls[16], lq[16];
#pragma unroll
    for (int j = 0; j < 16; j++) { ls[j] = 0.f; lq[j] = 0.f; }
#pragma unroll
    for (int rt = 0; rt < 2; rt++) {
        int r0 = nbase + rt * 16 + gid;
        int r1 = r0 + 8;
#pragma unroll
        for (int nt = 0; nt < 8; nt++) {
            int col = colw + nt * 8 + t4 * 2;
            float v0 = c[rt][nt][0], v1 = c[rt][nt][1];
            float v2 = c[rt][nt][2], v3 = c[rt][nt][3];
            if (r0 < NN) {
                float* dst = (col < 64) ? (out0 + (size_t)r0 * 64 + col)
                                        : (out1 + (size_t)r0 * 64 + col - 64);
                *reinterpret_cast<float2*>(dst) = make_float2(v0, v1);
                ls[nt * 2] += v0; lq[nt * 2] += v0 * v0;
                ls[nt * 2 + 1] += v1; lq[nt * 2 + 1] += v1 * v1;
            }
            if (r1 < NN) {
                float* dst = (col < 64) ? (out0 + (size_t)r1 * 64 + col)
                                        : (out1 + (size_t)r1 * 64 + col - 64);
                *reinterpret_cast<float2*>(dst) = make_float2(v2, v3);
                ls[nt * 2] += v2; lq[nt * 2] += v2 * v2;
                ls[nt * 2 + 1] += v3; lq[nt * 2 + 1] += v3 * v3;
            }
        }
    }
#pragma unroll
    for (int nt = 0; nt < 8; nt++) {
#pragma unroll
        for (int j = 0; j < 2; j++) {
            int col = colw + nt * 8 + t4 * 2 + j;
            atomicAdd(&s_sum[col], ls[nt * 2 + j]);
            atomicAdd(&s_sq[col], lq[nt * 2 + j]);
        }
    }
    __syncthreads();
    if (tid < Ncols) {
        atomicAdd(&g_sum[sumbase + tid], s_sum[tid]);
        atomicAdd(&g_sq[sumbase + tid], s_sq[tid]);
    }
}

// ---------------- bn+elu on h1 (grid-stride, scale/shift computed in-block from slot 0) ----------------
__global__ void __launch_bounds__(256) bnelu_kernel(const float* __restrict__ g1,
                                                    const float* __restrict__ b1) {
    __shared__ float sc[64], sh[64];
    int tid = threadIdx.x;
    if (tid < 64) {
        float mu  = g_sum[tid] * (1.0f / NN);
        float var = g_sq[tid] * (1.0f / NN) - mu * mu;
        float s = g1[tid] * rsqrtf(var + 1e-5f);
        sc[tid] = s;
        sh[tid] = b1[tid] - mu * s;
    }
    __syncthreads();
    for (int i = blockIdx.x * 256 + tid; i < NN * 64; i += gridDim.x * 256) {
        int o = i & 63;
        int n = i >> 6;
        float v = g_h[i] * sc[o] + sh[o];
        float e = (v > 0.f) ? v : expm1f(v);
        g_h[i] = e;
        g_Ah[(size_t)n * K2 + 512 + o] = __float2half(e);
    }
}

// ---------------- final: out = elu( BN(h2) + BN(skip) ), scale/shift from slots 1,2 ----------------
__global__ void __launch_bounds__(256) final_kernel(const float* __restrict__ gsk,
                                                    const float* __restrict__ bsk,
                                                    const float* __restrict__ g2,
                                                    const float* __restrict__ b2,
                                                    float* __restrict__ out) {
    __shared__ float sc1[64], sh1[64], sc2[64], sh2[64];
    int tid = threadIdx.x;
    if (tid < 64) {
        float mu  = g_sum[64 + tid] * (1.0f / NN);
        float var = g_sq[64 + tid] * (1.0f / NN) - mu * mu;
        float s = gsk[tid] * rsqrtf(var + 1e-5f);
        sc1[tid] = s;
        sh1[tid] = bsk[tid] - mu * s;
        mu  = g_sum[128 + tid] * (1.0f / NN);
        var = g_sq[128 + tid] * (1.0f / NN) - mu * mu;
        s = g2[tid] * rsqrtf(var + 1e-5f);
        sc2[tid] = s;
        sh2[tid] = b2[tid] - mu * s;
    }
    __syncthreads();
    for (int i = blockIdx.x * 256 + tid; i < NN * 64; i += gridDim.x * 256) {
        int o = i & 63;
        float h2 = g_h[i] * sc2[o] + sh2[o];
        float s  = g_skip[i] * sc1[o] + sh1[o];
        float v = h2 + s;
        out[i] = (v > 0.f) ? v : expm1f(v);
    }
}

extern "C" void kernel_launch(void* const* d_in, const int* in_sizes, int n_in,
                              void* d_out, int out_size) {
    const float* x     = (const float*)d_in[0];
    const int*   ei    = (const int*)d_in[1];
    const float* ea    = (const float*)d_in[2];
    const float* W1    = (const float*)d_in[3];
    const float* root1 = (const float*)d_in[4];
    const float* g1    = (const float*)d_in[5];
    const float* b1    = (const float*)d_in[6];
    const float* W2    = (const float*)d_in[7];
    const float* root2 = (const float*)d_in[8];
    const float* g2    = (const float*)d_in[9];
    const float* b2    = (const float*)d_in[10];
    const float* Wsk   = (const float*)d_in[11];
    const float* gsk   = (const float*)d_in[12];
    const float* bsk   = (const float*)d_in[13];
    float* out = (float*)d_out;

    void *deg_p, *sum_p, *sq_p, *ah_p, *wt1_p, *wt2_p, *h_p, *skip_p;
    cudaGetSymbolAddress(&deg_p, g_deg);
    cudaGetSymbolAddress(&sum_p, g_sum);
    cudaGetSymbolAddress(&sq_p, g_sq);
    cudaGetSymbolAddress(&ah_p, g_Ah);
    cudaGetSymbolAddress(&wt1_p, g_Wt1);
    cudaGetSymbolAddress(&wt2_p, g_Wt2);
    cudaGetSymbolAddress(&h_p, g_h);
    cudaGetSymbolAddress(&skip_p, g_skip);

    int smem1 = N1 * (K1 + 8) * 2;   // 83,968 B
    int smem2 = N2 * (K2 + 8) * 2;   // 74,752 B
    cudaFuncSetAttribute(gemm_mma_kernel, cudaFuncAttributeMaxDynamicSharedMemorySize, smem1);

    cudaMemsetAsync(deg_p, 0, sizeof(int) * NN, 0);
    cudaMemsetAsync(sum_p, 0, sizeof(float) * 192, 0);
    cudaMemsetAsync(sq_p, 0, sizeof(float) * 192, 0);

    // CSR build (parallel scan)
    hist_kernel<<<(EE + 255) / 256, 256>>>(ei);
    scan_partial_kernel<<<NB, 1024>>>();
    scan_add_kernel<<<NB, 1024>>>();
    scatter_kernel<<<(EE + 255) / 256, 256>>>(ei, ea);

    // ---- layer 1 ----
    edge_agg1_kernel<<<(NN + 7) / 8, 256>>>(x);
    wprep_kernel<<<(N1 * K1 + N2 * K2 + 255) / 256, 256>>>(W1, root1, Wsk, W2, root2);
    gemm_mma_kernel<<<(NN + 127) / 128, 256, smem1>>>((const __half*)ah_p, K1,
                                                      (const __half*)wt1_p, N1, 128,
                                                      (float*)h_p, (float*)skip_p, 0);
    bnelu_kernel<<<1184, 256>>>(g1, b1);

    // ---- layer 2 ----
    edge_agg2_kernel<<<(NN + 7) / 8, 256>>>();
    gemm_mma_kernel<<<(NN + 255) / 256, 256, smem2>>>((const __half*)ah_p, K2,
                                                      (const __half*)wt2_p, N2, 256,
                                                      (float*)h_p, (float*)h_p, 128);
    final_kernel<<<1184, 256>>>(gsk, bsk, g2, b2, out);
    (void)n_in; (void)in_sizes; (void)out_size;
}